// round 13
// baseline (speedup 1.0000x reference)
#include <cuda_runtime.h>
#include <cstdint>

#define GRID_H 13
#define GRID_W 13
#define NBOX   5
#define NELEM  85
#define NT     50
#define NTPAD  56
#define CPB    845                      // cells per batch
#define NBATCH 256

#define NWARPS 16                       // 512-thread blocks
#define BLOCK_CELLS 64
#define TOTAL_CELLS (NBATCH * CPB)      // 216320 = 3380 * 64 exactly
#define NBLOCKS (TOTAL_CELLS / BLOCK_CELLS)      // 3380
#define SPAN_FLOATS (BLOCK_CELLS * NELEM)        // 5440
#define SPAN_BYTES  (SPAN_FLOATS * 4)            // 21760 (16B multiple)

#define FULL 0xFFFFFFFFu

__constant__ float c_anchors[10] = {
    0.57273f, 0.677385f, 1.87446f, 2.06253f, 3.33843f,
    5.47434f, 7.88282f, 3.52778f, 9.77052f, 9.16828f
};

// 5 accumulators on distinct L2 lines: 0 nb_coord, 1 nb_conf, 2 s_xywh, 3 s_conf, 4 s_class
__device__ float    g_acc[5 * 32];
__device__ unsigned g_done;

__device__ __forceinline__ float fast_sigmoid(float x) {
    return __fdividef(1.0f, 1.0f + __expf(-x));
}

__global__ __launch_bounds__(32 * NWARPS)
void yolo_loss_kernel(const float* __restrict__ y_true,
                      const float* __restrict__ y_pred,
                      const float* __restrict__ true_boxes,
                      float* __restrict__ out) {
    const int tid  = threadIdx.x;
    const int warp = tid >> 5;
    const int lane = tid & 31;
    const int g    = lane >> 3;          // group = cell within warp's 4
    const int s    = lane & 7;           // sublane within group

    // ---- shared (static total ~46 KB, under 48 KB limit) ----
    __shared__ __align__(16) float s_p[SPAN_FLOATS];   // y_pred span (flat, stride 85)
    __shared__ __align__(16) float s_t[SPAN_FLOATS];   // y_true span
    __shared__ float4 s_ext[2 * NTPAD];                // box extents, up to 2 batches
    __shared__ float  s_b375[2 * NTPAD];
    __shared__ float  s_part[NWARPS][4];
    __shared__ __align__(8) unsigned long long s_mbar;

    const uint32_t mbar = (uint32_t)__cvta_generic_to_shared(&s_mbar);

    // ---- TMA bulk copy of both spans (single producer thread) ----
    if (tid == 0) {
        asm volatile("mbarrier.init.shared.b64 [%0], %1;" :: "r"(mbar), "r"(1) : "memory");
    }
    __syncthreads();
    if (tid == 0) {
        asm volatile("mbarrier.arrive.expect_tx.shared.b64 _, [%0], %1;"
                     :: "r"(mbar), "r"(2u * SPAN_BYTES) : "memory");
        const uint32_t dp = (uint32_t)__cvta_generic_to_shared(s_p);
        const uint32_t dt = (uint32_t)__cvta_generic_to_shared(s_t);
        const char* gp = (const char*)y_pred + (size_t)blockIdx.x * SPAN_BYTES;
        const char* gt = (const char*)y_true + (size_t)blockIdx.x * SPAN_BYTES;
        asm volatile("cp.async.bulk.shared::cta.global.mbarrier::complete_tx::bytes "
                     "[%0], [%1], %2, [%3];"
                     :: "r"(dp), "l"(gp), "r"((unsigned)SPAN_BYTES), "r"(mbar) : "memory");
        asm volatile("cp.async.bulk.shared::cta.global.mbarrier::complete_tx::bytes "
                     "[%0], [%1], %2, [%3];"
                     :: "r"(dt), "l"(gt), "r"((unsigned)SPAN_BYTES), "r"(mbar) : "memory");
    }

    // ---- true-box tables for both possibly-touched batches (overlaps with TMA) ----
    const int gcell0 = blockIdx.x * BLOCK_CELLS;
    const int b0 = gcell0 / CPB;
    const int b1 = (gcell0 + BLOCK_CELLS - 1) / CPB;
    if (tid < 2 * NTPAD) {
        const int half = tid / NTPAD;
        const int t    = tid - half * NTPAD;
        const int bb   = half ? b1 : b0;
        float4 v = (t < NT) ? ((const float4*)(true_boxes + bb * NT * 4))[t]
                            : make_float4(1e9f, 0.f, 0.f, 0.f);
        s_ext[tid]  = make_float4(v.x - v.z * 0.5f, v.x + v.z * 0.5f,
                                  v.y - v.w * 0.5f, v.y + v.w * 0.5f);
        s_b375[tid] = (t < NT) ? 0.375f * v.z * v.w : 3e38f;
    }
    __syncthreads();   // s_ext visible

    // ---- wait for TMA completion (acquire) ----
    {
        uint32_t done;
        asm volatile("{\n\t.reg .pred p;\n\t"
                     "mbarrier.try_wait.parity.acquire.cta.shared::cta.b64 p, [%1], %2;\n\t"
                     "selp.b32 %0, 1, 0, p;\n\t}"
                     : "=r"(done) : "r"(mbar), "r"(0u) : "memory");
        while (!done) {
            asm volatile("{\n\t.reg .pred p;\n\t"
                         "mbarrier.try_wait.parity.acquire.cta.shared::cta.b64 p, [%1], %2;\n\t"
                         "selp.b32 %0, 1, 0, p;\n\t}"
                         : "=r"(done) : "r"(mbar), "r"(0u) : "memory");
        }
    }

    // ---- own-cell assignment (group g owns block-cell warp*4+g) ----
    const int cidx  = warp * 4 + g;                  // 0..63
    const int gcell = gcell0 + cidx;                 // always valid (exact tiling)
    const int bown  = gcell / CPB;
    const int cell  = gcell - bown * CPB;
    const int tb    = (bown == b0) ? 0 : NTPAD;
    const int gb    = cidx * NELEM;                  // flat stride 85

    // ---- box scalars (broadcast LDS) ----
    const float p0 = s_p[gb + 0], p1 = s_p[gb + 1], p2 = s_p[gb + 2],
                p3 = s_p[gb + 3], p4 = s_p[gb + 4];
    const float txo = s_t[gb + 0], tyo = s_t[gb + 1];
    const float two = s_t[gb + 2], tho = s_t[gb + 3];
    const float tco = s_t[gb + 4];

    // ---- classes: e = 5 + s + 8i covers exactly [5,85) ----
    float se = 0.0f;
    float av = -1.0f; int ai = 0x7FFFFFFF;
    #pragma unroll
    for (int i = 0; i < 10; i++) {
        const int e = 5 + s + 8 * i;
        se += __expf(s_p[gb + e]);
        const float tte = s_t[gb + e];
        if (tte > av) { av = tte; ai = e; }
    }
    // intra-group butterflies (3 steps; first-max via min index on ties)
    #pragma unroll
    for (int o = 1; o < 8; o <<= 1) se += __shfl_xor_sync(FULL, se, o);
    #pragma unroll
    for (int o = 1; o < 8; o <<= 1) {
        const float v2 = __shfl_xor_sync(FULL, av, o);
        const int   i2 = __shfl_xor_sync(FULL, ai, o);
        if (v2 > av || (v2 == av && i2 < ai)) { av = v2; ai = i2; }
    }

    // ---- predicted box (redundant within group: free in warp issue) ----
    const int boxo = cell % NBOX;
    const int wo   = (cell / NBOX) % GRID_W;
    const int ho   = cell / (NBOX * GRID_W);
    const float px = fast_sigmoid(p0) + (float)wo;
    const float py = fast_sigmoid(p1) + (float)ho;
    const float pw = __expf(p2) * c_anchors[2 * boxo];
    const float ph = __expf(p3) * c_anchors[2 * boxo + 1];
    const float pc = fast_sigmoid(p4);
    const float pxmin = px - pw * 0.5f, pxmax = px + pw * 0.5f;
    const float pymin = py - ph * 0.5f, pymax = py + ph * 0.5f;
    const float parea = pw * ph;
    const float p375  = 0.375f * parea;

    // ---- divisionless best-IoU >= 0.6 test: 7 boxes per sublane ----
    bool hit = false;
    #pragma unroll
    for (int j = 0; j < 7; j++) {
        const int t = tb + s + 8 * j;
        const float4 e = s_ext[t];
        const float iw = fmaxf(fminf(pxmax, e.y) - fmaxf(pxmin, e.x), 0.0f);
        const float ih = fmaxf(fminf(pymax, e.w) - fmaxf(pymin, e.z), 0.0f);
        hit = hit || (iw * ih >= p375 + s_b375[t]);
    }
    const unsigned bal  = __ballot_sync(FULL, hit);
    const bool     hitg = ((bal >> (g * 8)) & 0xFFu) != 0u;

    // ---- epilogue ----
    const float lt = s_p[gb + ai];               // LDS broadcast (ai uniform in group)
    const float ce = __logf(se) - lt;

    const float iw = fmaxf(fminf(pxmax, txo + two * 0.5f) - fmaxf(pxmin, txo - two * 0.5f), 0.0f);
    const float ih = fmaxf(fminf(pymax, tyo + tho * 0.5f) - fmaxf(pymin, tyo - tho * 0.5f), 0.0f);
    const float ia = iw * ih;
    const float iou = __fdividef(ia, parea + two * tho - ia);

    const float cm = tco;                        // coord mask == class mask
    const float tc = iou * tco;
    const float fm = (hitg ? 0.0f : 1.0f) * (1.0f - tco) + 5.0f * tc;

    const bool use = (s == 0);
    // packed counts: nb_coord + 128 * nb_conf (exact integers throughout)
    float accC = ((use && cm > 0.0f) ? 1.0f : 0.0f)
               + ((use && fm > 0.0f) ? 128.0f : 0.0f);
    float acc2 = use ? ((txo - px) * (txo - px) + (tyo - py) * (tyo - py)
                      + (two - pw) * (two - pw) + (tho - ph) * (tho - ph)) * cm : 0.0f;
    float acc3 = use ? (tc - pc) * (tc - pc) * fm : 0.0f;                // s_conf
    float acc4 = use ? ce * cm : 0.0f;                                   // s_class

    // ---- reduce group leaders -> lane 0 ----
    #pragma unroll
    for (int o = 8; o < 32; o <<= 1) {
        accC += __shfl_xor_sync(FULL, accC, o);
        acc2 += __shfl_xor_sync(FULL, acc2, o);
        acc3 += __shfl_xor_sync(FULL, acc3, o);
        acc4 += __shfl_xor_sync(FULL, acc4, o);
    }

    if (lane == 0) {
        s_part[warp][0] = accC; s_part[warp][1] = acc2;
        s_part[warp][2] = acc3; s_part[warp][3] = acc4;
    }
    __syncthreads();
    if (warp == 0) {
        float v[4];
        #pragma unroll
        for (int i = 0; i < 4; i++) {
            v[i] = (lane < NWARPS) ? s_part[lane][i] : 0.0f;
            #pragma unroll
            for (int o = 8; o > 0; o >>= 1) v[i] += __shfl_down_sync(FULL, v[i], o);
        }
        if (lane == 0) {
            const float c1 = floorf(v[0] * (1.0f / 128.0f));   // nb_conf (exact)
            const float c0 = v[0] - c1 * 128.0f;               // nb_coord
            atomicAdd(&g_acc[0 * 32], c0);
            atomicAdd(&g_acc[1 * 32], c1);
            atomicAdd(&g_acc[2 * 32], v[1]);
            atomicAdd(&g_acc[3 * 32], v[2]);
            atomicAdd(&g_acc[4 * 32], v[3]);
        }
    }

    // ---- last-block finalize (single launch) ----
    if (tid == 0) {
        __threadfence();
        const unsigned t = atomicAdd(&g_done, 1u);
        if (t == (unsigned)(NBLOCKS - 1)) {
            __threadfence();
            float a[5];
            #pragma unroll
            for (int i = 0; i < 5; i++) a[i] = atomicAdd(&g_acc[i * 32], 0.0f);
            const float nbc = a[0] + 1e-6f;
            const float nbf = a[1] + 1e-6f;
            out[0] = a[2] / nbc * 0.5f          // loss_xy + loss_wh
                   + a[3] / nbf * 0.5f          // loss_conf
                   + a[4] / nbc;                // loss_class (nb_class == nb_coord)
            #pragma unroll
            for (int i = 0; i < 5; i++) g_acc[i * 32] = 0.0f;
            g_done = 0u;
        }
    }
}

extern "C" void kernel_launch(void* const* d_in, const int* in_sizes, int n_in,
                              void* d_out, int out_size) {
    const float* y_true     = (const float*)d_in[0];
    const float* y_pred     = (const float*)d_in[1];
    const float* true_boxes = (const float*)d_in[2];
    float* out = (float*)d_out;

    yolo_loss_kernel<<<NBLOCKS, 32 * NWARPS>>>(y_true, y_pred, true_boxes, out);
}

// round 15
// speedup vs baseline: 1.0759x; 1.0759x over previous
#include <cuda_runtime.h>
#include <cstdint>

#define GRID_H 13
#define GRID_W 13
#define NBOX   5
#define NELEM  85
#define NT     50
#define NTPAD  56
#define CPB    845                      // cells per batch
#define NBATCH 256

#define NWARPS 8                        // 256-thread blocks
#define TILE_CELLS 32
#define TILES_PER_CTA 4
#define CTA_CELLS (TILE_CELLS * TILES_PER_CTA)   // 128
#define TOTAL_CELLS (NBATCH * CPB)               // 216320 = 1690 * 128 exactly
#define NBLOCKS (TOTAL_CELLS / CTA_CELLS)        // 1690
#define TILE_FLOATS (TILE_CELLS * NELEM)         // 2720
#define TILE_BYTES  (TILE_FLOATS * 4)            // 10880 (16B multiple)

#define PACK 1024.0f                    // count packing: nb_coord + PACK*nb_conf (both <= 128)

#define FULL 0xFFFFFFFFu

__constant__ float c_anchors[10] = {
    0.57273f, 0.677385f, 1.87446f, 2.06253f, 3.33843f,
    5.47434f, 7.88282f, 3.52778f, 9.77052f, 9.16828f
};

// 5 accumulators on distinct L2 lines: 0 nb_coord, 1 nb_conf, 2 s_xywh, 3 s_conf, 4 s_class
__device__ float    g_acc[5 * 32];
__device__ unsigned g_done;

__device__ __forceinline__ float fast_sigmoid(float x) {
    return __fdividef(1.0f, 1.0f + __expf(-x));
}

__global__ __launch_bounds__(32 * NWARPS)
void yolo_loss_kernel(const float* __restrict__ y_true,
                      const float* __restrict__ y_pred,
                      const float* __restrict__ true_boxes,
                      float* __restrict__ out) {
    const int tid  = threadIdx.x;
    const int warp = tid >> 5;
    const int lane = tid & 31;
    const int g    = lane >> 3;          // group = cell within warp's 4
    const int s    = lane & 7;           // sublane within group

    // ---- shared (~46 KB static): double-buffered tile pair + tables ----
    __shared__ __align__(16) float s_buf[2][2][TILE_FLOATS];  // [stage][pred/true][float]
    __shared__ float4 s_ext[2 * NTPAD];
    __shared__ float  s_b375[2 * NTPAD];
    __shared__ float  s_part[NWARPS][4];
    __shared__ __align__(8) unsigned long long s_mbar[2];

    const uint32_t mb0 = (uint32_t)__cvta_generic_to_shared(&s_mbar[0]);
    const uint32_t mb1 = (uint32_t)__cvta_generic_to_shared(&s_mbar[1]);

    const int gcell0 = blockIdx.x * CTA_CELLS;
    const size_t byte0 = (size_t)gcell0 * NELEM * 4;

    if (tid == 0) {
        asm volatile("mbarrier.init.shared.b64 [%0], %1;" :: "r"(mb0), "r"(1) : "memory");
        asm volatile("mbarrier.init.shared.b64 [%0], %1;" :: "r"(mb1), "r"(1) : "memory");
    }
    __syncthreads();

    // ---- issue TMA for tiles 0 and 1 ----
    if (tid == 0) {
        #pragma unroll
        for (int t0 = 0; t0 < 2; t0++) {
            const uint32_t mb = t0 ? mb1 : mb0;
            asm volatile("mbarrier.arrive.expect_tx.shared.b64 _, [%0], %1;"
                         :: "r"(mb), "r"(2u * TILE_BYTES) : "memory");
            const uint32_t dp = (uint32_t)__cvta_generic_to_shared(&s_buf[t0][0][0]);
            const uint32_t dt = (uint32_t)__cvta_generic_to_shared(&s_buf[t0][1][0]);
            const char* gp = (const char*)y_pred + byte0 + (size_t)t0 * TILE_BYTES;
            const char* gt = (const char*)y_true + byte0 + (size_t)t0 * TILE_BYTES;
            asm volatile("cp.async.bulk.shared::cta.global.mbarrier::complete_tx::bytes "
                         "[%0], [%1], %2, [%3];"
                         :: "r"(dp), "l"(gp), "r"((unsigned)TILE_BYTES), "r"(mb) : "memory");
            asm volatile("cp.async.bulk.shared::cta.global.mbarrier::complete_tx::bytes "
                         "[%0], [%1], %2, [%3];"
                         :: "r"(dt), "l"(gt), "r"((unsigned)TILE_BYTES), "r"(mb) : "memory");
        }
    }

    // ---- true-box tables for the (at most 2) batches this CTA touches ----
    const int b0 = gcell0 / CPB;
    const int b1 = (gcell0 + CTA_CELLS - 1) / CPB;
    if (tid < 2 * NTPAD) {
        const int half = tid / NTPAD;
        const int t    = tid - half * NTPAD;
        const int bb   = half ? b1 : b0;
        float4 v = (t < NT) ? ((const float4*)(true_boxes + bb * NT * 4))[t]
                            : make_float4(1e9f, 0.f, 0.f, 0.f);
        s_ext[tid]  = make_float4(v.x - v.z * 0.5f, v.x + v.z * 0.5f,
                                  v.y - v.w * 0.5f, v.y + v.w * 0.5f);
        s_b375[tid] = (t < NT) ? 0.375f * v.z * v.w : 3e38f;
    }
    __syncthreads();   // tables visible

    // ---- per-thread accumulators across all 4 tiles ----
    float accC = 0.f, acc2 = 0.f, acc3 = 0.f, acc4 = 0.f;
    const int cidx = warp * 4 + g;       // cell within tile (0..31)
    const bool use = (s == 0);

    #pragma unroll
    for (int t = 0; t < TILES_PER_CTA; t++) {
        const int      stage  = t & 1;
        const uint32_t mb     = stage ? mb1 : mb0;
        const uint32_t parity = (unsigned)(t >> 1) & 1u;

        // wait for tile t's data (acquire)
        {
            uint32_t done;
            do {
                asm volatile("{\n\t.reg .pred p;\n\t"
                             "mbarrier.try_wait.parity.acquire.cta.shared::cta.b64 p, [%1], %2;\n\t"
                             "selp.b32 %0, 1, 0, p;\n\t}"
                             : "=r"(done) : "r"(mb), "r"(parity) : "memory");
            } while (!done);
        }

        const float* sp = &s_buf[stage][0][0];
        const float* st = &s_buf[stage][1][0];

        const int gcell = gcell0 + t * TILE_CELLS + cidx;
        const int bown  = gcell / CPB;
        const int cell  = gcell - bown * CPB;
        const int tb    = (bown == b0) ? 0 : NTPAD;
        const int gb    = cidx * NELEM;

        // box scalars (broadcast LDS)
        const float p0 = sp[gb + 0], p1 = sp[gb + 1], p2 = sp[gb + 2],
                    p3 = sp[gb + 3], p4 = sp[gb + 4];
        const float txo = st[gb + 0], tyo = st[gb + 1];
        const float two = st[gb + 2], tho = st[gb + 3];
        const float tco = st[gb + 4];

        // classes: e = 5 + s + 8i covers exactly [5,85)
        float se = 0.0f;
        float av = -1.0f; int ai = 0x7FFFFFFF;
        #pragma unroll
        for (int i = 0; i < 10; i++) {
            const int e = 5 + s + 8 * i;
            se += __expf(sp[gb + e]);
            const float tte = st[gb + e];
            if (tte > av) { av = tte; ai = e; }
        }
        #pragma unroll
        for (int o = 1; o < 8; o <<= 1) se += __shfl_xor_sync(FULL, se, o);
        #pragma unroll
        for (int o = 1; o < 8; o <<= 1) {
            const float v2 = __shfl_xor_sync(FULL, av, o);
            const int   i2 = __shfl_xor_sync(FULL, ai, o);
            if (v2 > av || (v2 == av && i2 < ai)) { av = v2; ai = i2; }
        }

        // predicted box (redundant within group)
        const int boxo = cell % NBOX;
        const int wo   = (cell / NBOX) % GRID_W;
        const int ho   = cell / (NBOX * GRID_W);
        const float px = fast_sigmoid(p0) + (float)wo;
        const float py = fast_sigmoid(p1) + (float)ho;
        const float pw = __expf(p2) * c_anchors[2 * boxo];
        const float ph = __expf(p3) * c_anchors[2 * boxo + 1];
        const float pc = fast_sigmoid(p4);
        const float pxmin = px - pw * 0.5f, pxmax = px + pw * 0.5f;
        const float pymin = py - ph * 0.5f, pymax = py + ph * 0.5f;
        const float parea = pw * ph;
        const float p375  = 0.375f * parea;

        // divisionless best-IoU >= 0.6 test: 7 boxes per sublane
        bool hit = false;
        #pragma unroll
        for (int j = 0; j < 7; j++) {
            const int tt = tb + s + 8 * j;
            const float4 e = s_ext[tt];
            const float iw = fmaxf(fminf(pxmax, e.y) - fmaxf(pxmin, e.x), 0.0f);
            const float ih = fmaxf(fminf(pymax, e.w) - fmaxf(pymin, e.z), 0.0f);
            hit = hit || (iw * ih >= p375 + s_b375[tt]);
        }
        const unsigned bal  = __ballot_sync(FULL, hit);
        const bool     hitg = ((bal >> (g * 8)) & 0xFFu) != 0u;

        // epilogue
        const float lt = sp[gb + ai];
        const float ce = __logf(se) - lt;

        const float iw = fmaxf(fminf(pxmax, txo + two * 0.5f) - fmaxf(pxmin, txo - two * 0.5f), 0.0f);
        const float ih = fmaxf(fminf(pymax, tyo + tho * 0.5f) - fmaxf(pymin, tyo - tho * 0.5f), 0.0f);
        const float ia = iw * ih;
        const float iou = __fdividef(ia, parea + two * tho - ia);

        const float cm = tco;                    // coord mask == class mask
        const float tc = iou * tco;
        const float fm = (hitg ? 0.0f : 1.0f) * (1.0f - tco) + 5.0f * tc;

        accC += ((use && cm > 0.0f) ? 1.0f : 0.0f)
              + ((use && fm > 0.0f) ? PACK : 0.0f);      // packed counts (1024 > 128 max)
        acc2 += use ? ((txo - px) * (txo - px) + (tyo - py) * (tyo - py)
                     + (two - pw) * (two - pw) + (tho - ph) * (tho - ph)) * cm : 0.0f;
        acc3 += use ? (tc - pc) * (tc - pc) * fm : 0.0f;
        acc4 += use ? ce * cm : 0.0f;

        // all warps done reading this stage; reissue it for tile t+2
        __syncthreads();
        if (t + 2 < TILES_PER_CTA && tid == 0) {
            asm volatile("mbarrier.arrive.expect_tx.shared.b64 _, [%0], %1;"
                         :: "r"(mb), "r"(2u * TILE_BYTES) : "memory");
            const uint32_t dp = (uint32_t)__cvta_generic_to_shared(&s_buf[stage][0][0]);
            const uint32_t dt = (uint32_t)__cvta_generic_to_shared(&s_buf[stage][1][0]);
            const char* gp = (const char*)y_pred + byte0 + (size_t)(t + 2) * TILE_BYTES;
            const char* gt = (const char*)y_true + byte0 + (size_t)(t + 2) * TILE_BYTES;
            asm volatile("cp.async.bulk.shared::cta.global.mbarrier::complete_tx::bytes "
                         "[%0], [%1], %2, [%3];"
                         :: "r"(dp), "l"(gp), "r"((unsigned)TILE_BYTES), "r"(mb) : "memory");
            asm volatile("cp.async.bulk.shared::cta.global.mbarrier::complete_tx::bytes "
                         "[%0], [%1], %2, [%3];"
                         :: "r"(dt), "l"(gt), "r"((unsigned)TILE_BYTES), "r"(mb) : "memory");
        }
    }

    // ---- reduce group leaders -> lane 0 ----
    #pragma unroll
    for (int o = 8; o < 32; o <<= 1) {
        accC += __shfl_xor_sync(FULL, accC, o);
        acc2 += __shfl_xor_sync(FULL, acc2, o);
        acc3 += __shfl_xor_sync(FULL, acc3, o);
        acc4 += __shfl_xor_sync(FULL, acc4, o);
    }

    if (lane == 0) {
        s_part[warp][0] = accC; s_part[warp][1] = acc2;
        s_part[warp][2] = acc3; s_part[warp][3] = acc4;
    }
    __syncthreads();
    if (warp == 0) {
        float v[4];
        #pragma unroll
        for (int i = 0; i < 4; i++) {
            v[i] = (lane < NWARPS) ? s_part[lane][i] : 0.0f;
            #pragma unroll
            for (int o = 4; o > 0; o >>= 1) v[i] += __shfl_down_sync(FULL, v[i], o);
        }
        if (lane == 0) {
            const float c1 = floorf(v[0] * (1.0f / PACK));     // nb_conf (exact)
            const float c0 = v[0] - c1 * PACK;                 // nb_coord (exact, <= 128)
            atomicAdd(&g_acc[0 * 32], c0);
            atomicAdd(&g_acc[1 * 32], c1);
            atomicAdd(&g_acc[2 * 32], v[1]);
            atomicAdd(&g_acc[3 * 32], v[2]);
            atomicAdd(&g_acc[4 * 32], v[3]);
        }
    }

    // ---- last-block finalize (single launch) ----
    if (tid == 0) {
        __threadfence();
        const unsigned t = atomicAdd(&g_done, 1u);
        if (t == (unsigned)(NBLOCKS - 1)) {
            __threadfence();
            float a[5];
            #pragma unroll
            for (int i = 0; i < 5; i++) a[i] = atomicAdd(&g_acc[i * 32], 0.0f);
            const float nbc = a[0] + 1e-6f;
            const float nbf = a[1] + 1e-6f;
            out[0] = a[2] / nbc * 0.5f          // loss_xy + loss_wh
                   + a[3] / nbf * 0.5f          // loss_conf
                   + a[4] / nbc;                // loss_class (nb_class == nb_coord)
            #pragma unroll
            for (int i = 0; i < 5; i++) g_acc[i * 32] = 0.0f;
            g_done = 0u;
        }
    }
}

extern "C" void kernel_launch(void* const* d_in, const int* in_sizes, int n_in,
                              void* d_out, int out_size) {
    const float* y_true     = (const float*)d_in[0];
    const float* y_pred     = (const float*)d_in[1];
    const float* true_boxes = (const float*)d_in[2];
    float* out = (float*)d_out;

    yolo_loss_kernel<<<NBLOCKS, 32 * NWARPS>>>(y_true, y_pred, true_boxes, out);
}

// round 16
// speedup vs baseline: 1.1098x; 1.0315x over previous
#include <cuda_runtime.h>
#include <cstdint>

#define GRID_H 13
#define GRID_W 13
#define NBOX   5
#define NELEM  85
#define NT     50
#define NTPAD  56
#define CPB    845                      // cells per batch
#define NBATCH 256

#define NWARPS 4                        // 128-thread blocks
#define TILE_CELLS 16
#define TILES_PER_CTA 8
#define CTA_CELLS (TILE_CELLS * TILES_PER_CTA)   // 128
#define TOTAL_CELLS (NBATCH * CPB)               // 216320 = 1690 * 128 exactly
#define NBLOCKS (TOTAL_CELLS / CTA_CELLS)        // 1690
#define TILE_FLOATS (TILE_CELLS * NELEM)         // 1360
#define TILE_BYTES  (TILE_FLOATS * 4)            // 5440 (16B multiple)

#define PACK 1024.0f                    // count packing: nb_coord + PACK*nb_conf (both <= 128)

#define FULL 0xFFFFFFFFu

__constant__ float c_anchors[10] = {
    0.57273f, 0.677385f, 1.87446f, 2.06253f, 3.33843f,
    5.47434f, 7.88282f, 3.52778f, 9.77052f, 9.16828f
};

// 5 accumulators on distinct L2 lines: 0 nb_coord, 1 nb_conf, 2 s_xywh, 3 s_conf, 4 s_class
__device__ float    g_acc[5 * 32];
__device__ unsigned g_done;

__device__ __forceinline__ float fast_sigmoid(float x) {
    return __fdividef(1.0f, 1.0f + __expf(-x));
}

__global__ __launch_bounds__(32 * NWARPS)
void yolo_loss_kernel(const float* __restrict__ y_true,
                      const float* __restrict__ y_pred,
                      const float* __restrict__ true_boxes,
                      float* __restrict__ out) {
    const int tid  = threadIdx.x;
    const int warp = tid >> 5;
    const int lane = tid & 31;
    const int g    = lane >> 3;          // group = cell within warp's 4
    const int s    = lane & 7;           // sublane within group

    // ---- shared (~24 KB static): double-buffered tile pair + tables ----
    __shared__ __align__(16) float s_buf[2][2][TILE_FLOATS];  // [stage][pred/true][float]
    __shared__ float4 s_ext[2 * NTPAD];
    __shared__ float  s_b375[2 * NTPAD];
    __shared__ float  s_part[NWARPS][4];
    __shared__ __align__(8) unsigned long long s_mbar[2];

    const uint32_t mb0 = (uint32_t)__cvta_generic_to_shared(&s_mbar[0]);
    const uint32_t mb1 = (uint32_t)__cvta_generic_to_shared(&s_mbar[1]);

    const int gcell0 = blockIdx.x * CTA_CELLS;
    const size_t byte0 = (size_t)gcell0 * NELEM * 4;

    if (tid == 0) {
        asm volatile("mbarrier.init.shared.b64 [%0], %1;" :: "r"(mb0), "r"(1) : "memory");
        asm volatile("mbarrier.init.shared.b64 [%0], %1;" :: "r"(mb1), "r"(1) : "memory");
    }
    __syncthreads();

    // ---- issue TMA for tiles 0 and 1 ----
    if (tid == 0) {
        #pragma unroll
        for (int t0 = 0; t0 < 2; t0++) {
            const uint32_t mb = t0 ? mb1 : mb0;
            asm volatile("mbarrier.arrive.expect_tx.shared.b64 _, [%0], %1;"
                         :: "r"(mb), "r"(2u * TILE_BYTES) : "memory");
            const uint32_t dp = (uint32_t)__cvta_generic_to_shared(&s_buf[t0][0][0]);
            const uint32_t dt = (uint32_t)__cvta_generic_to_shared(&s_buf[t0][1][0]);
            const char* gp = (const char*)y_pred + byte0 + (size_t)t0 * TILE_BYTES;
            const char* gt = (const char*)y_true + byte0 + (size_t)t0 * TILE_BYTES;
            asm volatile("cp.async.bulk.shared::cta.global.mbarrier::complete_tx::bytes "
                         "[%0], [%1], %2, [%3];"
                         :: "r"(dp), "l"(gp), "r"((unsigned)TILE_BYTES), "r"(mb) : "memory");
            asm volatile("cp.async.bulk.shared::cta.global.mbarrier::complete_tx::bytes "
                         "[%0], [%1], %2, [%3];"
                         :: "r"(dt), "l"(gt), "r"((unsigned)TILE_BYTES), "r"(mb) : "memory");
        }
    }

    // ---- true-box tables for the (at most 2) batches this CTA touches ----
    const int b0 = gcell0 / CPB;
    const int b1 = (gcell0 + CTA_CELLS - 1) / CPB;
    if (tid < 2 * NTPAD) {
        const int half = tid / NTPAD;
        const int t    = tid - half * NTPAD;
        const int bb   = half ? b1 : b0;
        float4 v = (t < NT) ? ((const float4*)(true_boxes + bb * NT * 4))[t]
                            : make_float4(1e9f, 0.f, 0.f, 0.f);
        s_ext[tid]  = make_float4(v.x - v.z * 0.5f, v.x + v.z * 0.5f,
                                  v.y - v.w * 0.5f, v.y + v.w * 0.5f);
        s_b375[tid] = (t < NT) ? 0.375f * v.z * v.w : 3e38f;
    }
    __syncthreads();   // tables visible

    // ---- per-thread accumulators across all 8 tiles ----
    float accC = 0.f, acc2 = 0.f, acc3 = 0.f, acc4 = 0.f;
    const int cidx = warp * 4 + g;       // cell within tile (0..15)
    const bool use = (s == 0);

    #pragma unroll
    for (int t = 0; t < TILES_PER_CTA; t++) {
        const int      stage  = t & 1;
        const uint32_t mb     = stage ? mb1 : mb0;
        const uint32_t parity = (unsigned)(t >> 1) & 1u;

        // wait for tile t's data (acquire)
        {
            uint32_t done;
            do {
                asm volatile("{\n\t.reg .pred p;\n\t"
                             "mbarrier.try_wait.parity.acquire.cta.shared::cta.b64 p, [%1], %2;\n\t"
                             "selp.b32 %0, 1, 0, p;\n\t}"
                             : "=r"(done) : "r"(mb), "r"(parity) : "memory");
            } while (!done);
        }

        const float* sp = &s_buf[stage][0][0];
        const float* st = &s_buf[stage][1][0];

        const int gcell = gcell0 + t * TILE_CELLS + cidx;
        const int bown  = gcell / CPB;
        const int cell  = gcell - bown * CPB;
        const int tb    = (bown == b0) ? 0 : NTPAD;
        const int gb    = cidx * NELEM;

        // box scalars (broadcast LDS)
        const float p0 = sp[gb + 0], p1 = sp[gb + 1], p2 = sp[gb + 2],
                    p3 = sp[gb + 3], p4 = sp[gb + 4];
        const float txo = st[gb + 0], tyo = st[gb + 1];
        const float two = st[gb + 2], tho = st[gb + 3];
        const float tco = st[gb + 4];

        // classes: e = 5 + s + 8i covers exactly [5,85)
        float se = 0.0f;
        float av = -1.0f; int ai = 0x7FFFFFFF;
        #pragma unroll
        for (int i = 0; i < 10; i++) {
            const int e = 5 + s + 8 * i;
            se += __expf(sp[gb + e]);
            const float tte = st[gb + e];
            if (tte > av) { av = tte; ai = e; }
        }
        #pragma unroll
        for (int o = 1; o < 8; o <<= 1) se += __shfl_xor_sync(FULL, se, o);
        #pragma unroll
        for (int o = 1; o < 8; o <<= 1) {
            const float v2 = __shfl_xor_sync(FULL, av, o);
            const int   i2 = __shfl_xor_sync(FULL, ai, o);
            if (v2 > av || (v2 == av && i2 < ai)) { av = v2; ai = i2; }
        }

        // predicted box (redundant within group)
        const int boxo = cell % NBOX;
        const int wo   = (cell / NBOX) % GRID_W;
        const int ho   = cell / (NBOX * GRID_W);
        const float px = fast_sigmoid(p0) + (float)wo;
        const float py = fast_sigmoid(p1) + (float)ho;
        const float pw = __expf(p2) * c_anchors[2 * boxo];
        const float ph = __expf(p3) * c_anchors[2 * boxo + 1];
        const float pc = fast_sigmoid(p4);
        const float pxmin = px - pw * 0.5f, pxmax = px + pw * 0.5f;
        const float pymin = py - ph * 0.5f, pymax = py + ph * 0.5f;
        const float parea = pw * ph;
        const float p375  = 0.375f * parea;

        // divisionless best-IoU >= 0.6 test: 7 boxes per sublane
        bool hit = false;
        #pragma unroll
        for (int j = 0; j < 7; j++) {
            const int tt = tb + s + 8 * j;
            const float4 e = s_ext[tt];
            const float iw = fmaxf(fminf(pxmax, e.y) - fmaxf(pxmin, e.x), 0.0f);
            const float ih = fmaxf(fminf(pymax, e.w) - fmaxf(pymin, e.z), 0.0f);
            hit = hit || (iw * ih >= p375 + s_b375[tt]);
        }
        const unsigned bal  = __ballot_sync(FULL, hit);
        const bool     hitg = ((bal >> (g * 8)) & 0xFFu) != 0u;

        // epilogue
        const float lt = sp[gb + ai];
        const float ce = __logf(se) - lt;

        const float iw = fmaxf(fminf(pxmax, txo + two * 0.5f) - fmaxf(pxmin, txo - two * 0.5f), 0.0f);
        const float ih = fmaxf(fminf(pymax, tyo + tho * 0.5f) - fmaxf(pymin, tyo - tho * 0.5f), 0.0f);
        const float ia = iw * ih;
        const float iou = __fdividef(ia, parea + two * tho - ia);

        const float cm = tco;                    // coord mask == class mask
        const float tc = iou * tco;
        const float fm = (hitg ? 0.0f : 1.0f) * (1.0f - tco) + 5.0f * tc;

        accC += ((use && cm > 0.0f) ? 1.0f : 0.0f)
              + ((use && fm > 0.0f) ? PACK : 0.0f);      // packed counts
        acc2 += use ? ((txo - px) * (txo - px) + (tyo - py) * (tyo - py)
                     + (two - pw) * (two - pw) + (tho - ph) * (tho - ph)) * cm : 0.0f;
        acc3 += use ? (tc - pc) * (tc - pc) * fm : 0.0f;
        acc4 += use ? ce * cm : 0.0f;

        // all warps done reading this stage; reissue it for tile t+2
        __syncthreads();
        if (t + 2 < TILES_PER_CTA && tid == 0) {
            asm volatile("mbarrier.arrive.expect_tx.shared.b64 _, [%0], %1;"
                         :: "r"(mb), "r"(2u * TILE_BYTES) : "memory");
            const uint32_t dp = (uint32_t)__cvta_generic_to_shared(&s_buf[stage][0][0]);
            const uint32_t dt = (uint32_t)__cvta_generic_to_shared(&s_buf[stage][1][0]);
            const char* gp = (const char*)y_pred + byte0 + (size_t)(t + 2) * TILE_BYTES;
            const char* gt = (const char*)y_true + byte0 + (size_t)(t + 2) * TILE_BYTES;
            asm volatile("cp.async.bulk.shared::cta.global.mbarrier::complete_tx::bytes "
                         "[%0], [%1], %2, [%3];"
                         :: "r"(dp), "l"(gp), "r"((unsigned)TILE_BYTES), "r"(mb) : "memory");
            asm volatile("cp.async.bulk.shared::cta.global.mbarrier::complete_tx::bytes "
                         "[%0], [%1], %2, [%3];"
                         :: "r"(dt), "l"(gt), "r"((unsigned)TILE_BYTES), "r"(mb) : "memory");
        }
    }

    // ---- reduce group leaders -> lane 0 ----
    #pragma unroll
    for (int o = 8; o < 32; o <<= 1) {
        accC += __shfl_xor_sync(FULL, accC, o);
        acc2 += __shfl_xor_sync(FULL, acc2, o);
        acc3 += __shfl_xor_sync(FULL, acc3, o);
        acc4 += __shfl_xor_sync(FULL, acc4, o);
    }

    if (lane == 0) {
        s_part[warp][0] = accC; s_part[warp][1] = acc2;
        s_part[warp][2] = acc3; s_part[warp][3] = acc4;
    }
    __syncthreads();
    if (warp == 0) {
        float v[4];
        #pragma unroll
        for (int i = 0; i < 4; i++) {
            v[i] = (lane < NWARPS) ? s_part[lane][i] : 0.0f;
            #pragma unroll
            for (int o = 2; o > 0; o >>= 1) v[i] += __shfl_down_sync(FULL, v[i], o);
        }
        if (lane == 0) {
            const float c1 = floorf(v[0] * (1.0f / PACK));     // nb_conf (exact)
            const float c0 = v[0] - c1 * PACK;                 // nb_coord (exact, <= 128)
            atomicAdd(&g_acc[0 * 32], c0);
            atomicAdd(&g_acc[1 * 32], c1);
            atomicAdd(&g_acc[2 * 32], v[1]);
            atomicAdd(&g_acc[3 * 32], v[2]);
            atomicAdd(&g_acc[4 * 32], v[3]);
        }
    }

    // ---- last-block finalize (single launch) ----
    if (tid == 0) {
        __threadfence();
        const unsigned t = atomicAdd(&g_done, 1u);
        if (t == (unsigned)(NBLOCKS - 1)) {
            __threadfence();
            float a[5];
            #pragma unroll
            for (int i = 0; i < 5; i++) a[i] = atomicAdd(&g_acc[i * 32], 0.0f);
            const float nbc = a[0] + 1e-6f;
            const float nbf = a[1] + 1e-6f;
            out[0] = a[2] / nbc * 0.5f          // loss_xy + loss_wh
                   + a[3] / nbf * 0.5f          // loss_conf
                   + a[4] / nbc;                // loss_class (nb_class == nb_coord)
            #pragma unroll
            for (int i = 0; i < 5; i++) g_acc[i * 32] = 0.0f;
            g_done = 0u;
        }
    }
}

extern "C" void kernel_launch(void* const* d_in, const int* in_sizes, int n_in,
                              void* d_out, int out_size) {
    const float* y_true     = (const float*)d_in[0];
    const float* y_pred     = (const float*)d_in[1];
    const float* true_boxes = (const float*)d_in[2];
    float* out = (float*)d_out;

    yolo_loss_kernel<<<NBLOCKS, 32 * NWARPS>>>(y_true, y_pred, true_boxes, out);
}